// round 1
// baseline (speedup 1.0000x reference)
#include <cuda_runtime.h>

// Problem constants
#define NWORDS 8192   // B*S
#define WLEN   20
#define VOCAB  256
#define E      64
#define H      256
#define TAPS   9      // k1: tap 0 | k3: taps 1..3 | k5: taps 4..8
#define H3     768

// Device scratch (allocation-free rule: __device__ globals)
__device__ float g_T[TAPS * VOCAB * H];      // [tap][char][h]  (2.25 MB)
__device__ float g_pooled[NWORDS * H3];      // [word][3H]      (25 MB)

// ---------------- packed f32x2 helpers ----------------
__device__ __forceinline__ void fma2(unsigned long long& d,
                                     unsigned long long a,
                                     unsigned long long b) {
  asm("fma.rn.f32x2 %0, %1, %2, %0;" : "+l"(d) : "l"(a), "l"(b));
}
__device__ __forceinline__ unsigned long long pack2(float x, float y) {
  unsigned long long r;
  asm("mov.b64 %0, {%1, %2};" : "=l"(r) : "f"(x), "f"(y));
  return r;
}
__device__ __forceinline__ float2 unpack2(unsigned long long a) {
  float2 v;
  asm("mov.b64 {%0, %1}, %2;" : "=f"(v.x), "=f"(v.y) : "l"(a));
  return v;
}

// ================= K0: build lookup tables =================
// T[t][c][h] = sum_e emb[c,e] * w_t[h,e,j(t)]
// grid: (TAPS, VOCAB/16), 256 threads (= h)
#define K0_WPAD 257
#define K0_SMEM ((E * K0_WPAD + 16 * E) * 4)

__global__ void __launch_bounds__(256) build_tables_kernel(
    const float* __restrict__ emb, const float* __restrict__ w1,
    const float* __restrict__ w3, const float* __restrict__ w5) {
  extern __shared__ float sm[];
  float* wts  = sm;                // [e][h] padded: wts[e*257 + h]
  float* embs = sm + E * K0_WPAD;  // [16][E]
  const int t   = blockIdx.x;
  const int c0  = blockIdx.y * 16;
  const int tid = threadIdx.x;

  for (int idx = tid; idx < E * H; idx += 256) {
    int e = idx & (E - 1);
    int h = idx >> 6;
    float v;
    if (t == 0)      v = w1[h * E + e];                    // [H,E,1]
    else if (t <= 3) v = w3[(h * E + e) * 3 + (t - 1)];    // [H,E,3]
    else             v = w5[(h * E + e) * 5 + (t - 4)];    // [H,E,5]
    wts[e * K0_WPAD + h] = v;
  }
  for (int idx = tid; idx < 16 * E; idx += 256)
    embs[idx] = emb[c0 * E + idx];
  __syncthreads();

  float acc[16];
#pragma unroll
  for (int c = 0; c < 16; ++c) acc[c] = 0.f;
  for (int e = 0; e < E; ++e) {
    float we = wts[e * K0_WPAD + tid];
#pragma unroll
    for (int c = 0; c < 16; ++c)
      acc[c] = fmaf(embs[c * E + e], we, acc[c]);
  }
#pragma unroll
  for (int c = 0; c < 16; ++c)
    g_T[(t * VOCAB + c0 + c) * H + tid] = acc[c];
}

// ================= K1: conv-as-lookup + relu + maxpool =================
// CTA: 16-h slice of all 9 tables in SMEM; processes 256 words.
// grid: (16 h-chunks, 32 word-chunks), 256 threads = 16 words x 16 h
#define HCHUNK 16
#define TPAD   17
#define A_SMEM ((TAPS * VOCAB * TPAD) * 4 + 16 * WLEN * 4)

__global__ void __launch_bounds__(256, 1) phase_a_kernel(
    const int* __restrict__ chars, const float* __restrict__ b1,
    const float* __restrict__ b3, const float* __restrict__ b5) {
  extern __shared__ float sm[];
  float* Ts = sm;                                     // [tap*256+c][17]
  int* chars_s = (int*)(sm + TAPS * VOCAB * TPAD);    // [16][20]
  const int hc  = blockIdx.x;   // 0..15
  const int wcb = blockIdx.y;   // 0..31
  const int tid = threadIdx.x;
  const int hl  = tid & 15;
  const int wl  = tid >> 4;
  const int h   = hc * HCHUNK + hl;

  for (int idx = tid; idx < TAPS * VOCAB * HCHUNK; idx += 256) {
    int tc = idx >> 4;
    int l  = idx & 15;
    Ts[tc * TPAD + l] = g_T[tc * H + hc * HCHUNK + l];
  }
  const float bb1 = b1[h], bb3 = b3[h], bb5 = b5[h];

  const float* T0 = Ts + hl;
  const float* T1 = Ts + 1 * VOCAB * TPAD + hl;
  const float* T2 = Ts + 2 * VOCAB * TPAD + hl;
  const float* T3 = Ts + 3 * VOCAB * TPAD + hl;
  const float* T4 = Ts + 4 * VOCAB * TPAD + hl;
  const float* T5 = Ts + 5 * VOCAB * TPAD + hl;
  const float* T6 = Ts + 6 * VOCAB * TPAD + hl;
  const float* T7 = Ts + 7 * VOCAB * TPAD + hl;
  const float* T8 = Ts + 8 * VOCAB * TPAD + hl;

  const int wbase = wcb * 256;
  for (int it = 0; it < 16; ++it) {
    __syncthreads();  // table load done (it=0) / previous readers done
    for (int idx = tid; idx < 16 * WLEN; idx += 256) {
      int w = idx / WLEN;
      int p = idx - w * WLEN;
      chars_s[idx] = chars[(wbase + it * 16 + w) * WLEN + p] * TPAD;
    }
    __syncthreads();

    int cc[WLEN];
#pragma unroll
    for (int p = 0; p < WLEN; ++p) cc[p] = chars_s[wl * WLEN + p];

    float m1 = -1e30f, m3 = -1e30f, m5 = -1e30f;
#pragma unroll
    for (int p = 0; p < WLEN; ++p) m1 = fmaxf(m1, T0[cc[p]]);
#pragma unroll
    for (int p = 0; p < WLEN; ++p) {
      float s = T2[cc[p]];
      if (p >= 1)        s += T1[cc[p - 1]];
      if (p < WLEN - 1)  s += T3[cc[p + 1]];
      m3 = fmaxf(m3, s);
    }
#pragma unroll
    for (int p = 0; p < WLEN; ++p) {
      float s = T6[cc[p]];
      if (p >= 2)        s += T4[cc[p - 2]];
      if (p >= 1)        s += T5[cc[p - 1]];
      if (p < WLEN - 1)  s += T7[cc[p + 1]];
      if (p < WLEN - 2)  s += T8[cc[p + 2]];
      m5 = fmaxf(m5, s);
    }

    const int n = wbase + it * 16 + wl;
    float* pr = g_pooled + n * H3;
    pr[h]          = fmaxf(m1 + bb1, 0.f);  // relu(max+b) == max(relu(.+b))
    pr[H + h]      = fmaxf(m3 + bb3, 0.f);
    pr[2 * H + h]  = fmaxf(m5 + bb5, 0.f);
  }
}

// ================= K2: out = pooled @ lw^T + lb (f32x2 GEMM) =================
// grid: NWORDS/NT blocks, 256 threads (= h). Each CTA: 32-word x 256-h tile.
#define NT     32
#define KT     64
#define LWPAD  257
#define PTPAD  34
#define B_SMEM ((KT * LWPAD + KT * PTPAD) * 4)

__global__ void __launch_bounds__(256) phase_b_kernel(
    const float* __restrict__ lw, const float* __restrict__ lb,
    float* __restrict__ out) {
  extern __shared__ float sm[];
  float* lws = sm;                 // [kk][h] padded 257
  float* pT  = sm + KT * LWPAD;    // [kk][w] padded 34 (8B-aligned rows)
  const int tid = threadIdx.x;
  const int n0  = blockIdx.x * NT;

  unsigned long long acc[NT / 2];
#pragma unroll
  for (int j = 0; j < NT / 2; ++j) acc[j] = 0ull;

  for (int kt = 0; kt < H3; kt += KT) {
    for (int i = 0; i < (KT * H) / 256; ++i) {
      int idx = i * 256 + tid;
      int hh  = idx >> 6;
      int kk  = idx & (KT - 1);
      lws[kk * LWPAD + hh] = lw[hh * H3 + kt + kk];   // coalesced (kk fastest)
    }
#pragma unroll
    for (int i = 0; i < (NT * KT) / 256; ++i) {
      int idx = i * 256 + tid;
      int w   = idx >> 6;
      int kk  = idx & (KT - 1);
      pT[kk * PTPAD + w] = g_pooled[(n0 + w) * H3 + kt + kk];
    }
    __syncthreads();
#pragma unroll 8
    for (int kk = 0; kk < KT; ++kk) {
      float wv = lws[kk * LWPAD + tid];
      unsigned long long wv2 = pack2(wv, wv);
      const unsigned long long* pr =
          reinterpret_cast<const unsigned long long*>(pT + kk * PTPAD);
#pragma unroll
      for (int j = 0; j < NT / 2; ++j) fma2(acc[j], pr[j], wv2);
    }
    __syncthreads();
  }

  const float lbv = lb[tid];
#pragma unroll
  for (int j = 0; j < NT / 2; ++j) {
    float2 v = unpack2(acc[j]);
    out[(n0 + 2 * j) * H + tid]     = v.x + lbv;
    out[(n0 + 2 * j + 1) * H + tid] = v.y + lbv;
  }
}

// ================= launch =================
extern "C" void kernel_launch(void* const* d_in, const int* in_sizes, int n_in,
                              void* d_out, int out_size) {
  const int*   chars = (const int*)d_in[0];
  const float* emb   = (const float*)d_in[1];
  const float* w1    = (const float*)d_in[2];
  const float* b1    = (const float*)d_in[3];
  const float* w3    = (const float*)d_in[4];
  const float* b3    = (const float*)d_in[5];
  const float* w5    = (const float*)d_in[6];
  const float* b5    = (const float*)d_in[7];
  const float* lw    = (const float*)d_in[8];
  const float* lb    = (const float*)d_in[9];
  float* out = (float*)d_out;

  cudaFuncSetAttribute(build_tables_kernel,
                       cudaFuncAttributeMaxDynamicSharedMemorySize, K0_SMEM);
  cudaFuncSetAttribute(phase_a_kernel,
                       cudaFuncAttributeMaxDynamicSharedMemorySize, A_SMEM);
  cudaFuncSetAttribute(phase_b_kernel,
                       cudaFuncAttributeMaxDynamicSharedMemorySize, B_SMEM);

  build_tables_kernel<<<dim3(TAPS, VOCAB / 16), 256, K0_SMEM>>>(emb, w1, w3, w5);
  phase_a_kernel<<<dim3(16, 32), 256, A_SMEM>>>(chars, b1, b3, b5);
  phase_b_kernel<<<NWORDS / NT, 256, B_SMEM>>>(lw, lb, out);
}

// round 2
// speedup vs baseline: 1.3364x; 1.3364x over previous
#include <cuda_runtime.h>

#define NWORDS 8192
#define WLEN   20
#define VOCAB  256
#define E      64
#define H      256
#define TAPS   9
#define H3     768

typedef unsigned long long ull;

__device__ float g_T[TAPS * VOCAB * H];   // [tap][char][h]
__device__ float g_pooled[NWORDS * H3];   // [word][3H]

// ---------------- packed f32x2 helpers ----------------
__device__ __forceinline__ void fma2(ull& d, ull a, ull b) {
  asm("fma.rn.f32x2 %0, %1, %2, %0;" : "+l"(d) : "l"(a), "l"(b));
}
__device__ __forceinline__ ull add2(ull a, ull b) {
  ull r; asm("add.rn.f32x2 %0, %1, %2;" : "=l"(r) : "l"(a), "l"(b)); return r;
}
__device__ __forceinline__ ull pack2(float x, float y) {
  ull r; asm("mov.b64 %0, {%1, %2};" : "=l"(r) : "f"(x), "f"(y)); return r;
}
__device__ __forceinline__ float2 u2(ull a) {
  float2 v; asm("mov.b64 {%0, %1}, %2;" : "=f"(v.x), "=f"(v.y) : "l"(a)); return v;
}
__device__ __forceinline__ ull lds64(const float* p) {
  return *reinterpret_cast<const ull*>(p);
}

// ================= K0: build lookup tables =================
// block = (tap, 16-h chunk), computes all 256 chars. 256 thr = 16 c-lanes x 16 h-lanes.
#define EPAD 68      // emb row pad (floats): 16B-aligned, bank-sep for adjacent c
#define WPD  66      // wts row pad (floats): 8B-aligned
#define K0_SMEM ((VOCAB * EPAD + 16 * WPD) * 4)

__global__ void __launch_bounds__(256) build_tables_kernel(
    const float* __restrict__ emb, const float* __restrict__ w1,
    const float* __restrict__ w3, const float* __restrict__ w5) {
  extern __shared__ float sm[];
  float* embs = sm;                    // [c][EPAD]
  float* wts  = sm + VOCAB * EPAD;     // [hl][WPD]
  const int t   = blockIdx.x;
  const int h0  = blockIdx.y * 16;
  const int tid = threadIdx.x;
  const int cl  = tid >> 4;            // 0..15
  const int hl  = tid & 15;            // 0..15

  // stage emb (coalesced float4)
  const float4* emb4 = reinterpret_cast<const float4*>(emb);
#pragma unroll
  for (int i = 0; i < 16; ++i) {
    int idx = i * 256 + tid;           // < 4096
    int c = idx >> 4, e4 = idx & 15;
    float4 v = emb4[c * 16 + e4];
    float* d = embs + c * EPAD + e4 * 4;
    d[0] = v.x; d[1] = v.y; d[2] = v.z; d[3] = v.w;
  }
  // stage this block's 16x64 weight slice
#pragma unroll
  for (int i = 0; i < 4; ++i) {
    int idx = i * 256 + tid;           // < 1024
    int hh = idx >> 6, e = idx & 63;
    int h = h0 + hh;
    float v;
    if (t == 0)      v = w1[h * E + e];
    else if (t <= 3) v = w3[(h * E + e) * 3 + (t - 1)];
    else             v = w5[(h * E + e) * 5 + (t - 4)];
    wts[hh * WPD + e] = v;
  }
  __syncthreads();

  ull acc2[16];
#pragma unroll
  for (int j = 0; j < 16; ++j) acc2[j] = 0ull;

  const ull* wrow = reinterpret_cast<const ull*>(wts + hl * WPD);
  const ull* eb   = reinterpret_cast<const ull*>(embs);
#pragma unroll 4
  for (int e2 = 0; e2 < E / 2; ++e2) {
    ull w2 = wrow[e2];
#pragma unroll
    for (int j = 0; j < 16; ++j)
      fma2(acc2[j], eb[(cl + 16 * j) * (EPAD / 2) + e2], w2);
  }
#pragma unroll
  for (int j = 0; j < 16; ++j) {
    float2 v = u2(acc2[j]);
    g_T[(t * VOCAB + cl + 16 * j) * H + h0 + hl] = v.x + v.y;
  }
}

// ================= K1: conv-as-lookup + relu + maxpool =================
// CTA: 16-h slice of all 9 tables in smem; 224 words (7 iters x 32 words).
// 256 thr = 32 w-lanes x 8 hp-lanes (2 h each, f32x2 lookups).
#define HCHUNK 16
#define TPAD   18
#define NIT    7
#define WPC    (NIT * 32)    // 224 words per CTA
#define A_SMEM ((TAPS * VOCAB * TPAD + 32 * WLEN) * 4)

__global__ void __launch_bounds__(256, 1) phase_a_kernel(
    const int* __restrict__ chars, const float* __restrict__ b1,
    const float* __restrict__ b3, const float* __restrict__ b5) {
  extern __shared__ float sm[];
  float* Ts = sm;                                    // [tap*256+c][18]
  int* chars_s = (int*)(sm + TAPS * VOCAB * TPAD);   // [32][20] (pre-scaled by TPAD)
  const int hc  = blockIdx.x;     // 0..15
  const int wcb = blockIdx.y;     // 0..36
  const int tid = threadIdx.x;
  const int hp2 = (tid & 7) * 2;  // h-pair within chunk
  const int wl  = tid >> 3;       // 0..31
  const int h0  = hc * HCHUNK;
  const int h   = h0 + hp2;

  // stage tables (144 scalar loads/thread)
  for (int idx = tid; idx < TAPS * VOCAB * HCHUNK; idx += 256) {
    int tc = idx >> 4, l = idx & 15;
    Ts[tc * TPAD + l] = g_T[tc * H + h0 + l];
  }
  const float bb1a = b1[h], bb1b = b1[h + 1];
  const float bb3a = b3[h], bb3b = b3[h + 1];
  const float bb5a = b5[h], bb5b = b5[h + 1];

  const float* B0 = Ts + hp2;
  const float* B1 = Ts + 1 * VOCAB * TPAD + hp2;
  const float* B2 = Ts + 2 * VOCAB * TPAD + hp2;
  const float* B3 = Ts + 3 * VOCAB * TPAD + hp2;
  const float* B4 = Ts + 4 * VOCAB * TPAD + hp2;
  const float* B5 = Ts + 5 * VOCAB * TPAD + hp2;
  const float* B6 = Ts + 6 * VOCAB * TPAD + hp2;
  const float* B7 = Ts + 7 * VOCAB * TPAD + hp2;
  const float* B8 = Ts + 8 * VOCAB * TPAD + hp2;

  const int wbase = wcb * WPC;
  for (int it = 0; it < NIT; ++it) {
    __syncthreads();   // tables staged (it=0) / previous readers done
    for (int idx = tid; idx < 32 * WLEN; idx += 256) {
      int w = idx / WLEN;
      int p = idx - w * WLEN;
      int n = wbase + it * 32 + w;
      if (n >= NWORDS) n = NWORDS - 1;
      chars_s[idx] = chars[n * WLEN + p] * TPAD;
    }
    __syncthreads();

    int cc[WLEN];
#pragma unroll
    for (int p = 0; p < WLEN; ++p) cc[p] = chars_s[wl * WLEN + p];

    float m1a = -3e38f, m1b = -3e38f;
    float m3a = -3e38f, m3b = -3e38f;
    float m5a = -3e38f, m5b = -3e38f;
#pragma unroll
    for (int p = 0; p < WLEN; ++p) {
      float2 v = u2(lds64(B0 + cc[p]));
      m1a = fmaxf(m1a, v.x); m1b = fmaxf(m1b, v.y);
    }
#pragma unroll
    for (int p = 0; p < WLEN; ++p) {
      ull s = lds64(B2 + cc[p]);
      if (p >= 1)        s = add2(s, lds64(B1 + cc[p - 1]));
      if (p < WLEN - 1)  s = add2(s, lds64(B3 + cc[p + 1]));
      float2 v = u2(s);
      m3a = fmaxf(m3a, v.x); m3b = fmaxf(m3b, v.y);
    }
#pragma unroll
    for (int p = 0; p < WLEN; ++p) {
      ull s = lds64(B6 + cc[p]);
      if (p >= 2)        s = add2(s, lds64(B4 + cc[p - 2]));
      if (p >= 1)        s = add2(s, lds64(B5 + cc[p - 1]));
      if (p < WLEN - 1)  s = add2(s, lds64(B7 + cc[p + 1]));
      if (p < WLEN - 2)  s = add2(s, lds64(B8 + cc[p + 2]));
      float2 v = u2(s);
      m5a = fmaxf(m5a, v.x); m5b = fmaxf(m5b, v.y);
    }

    const int n = wbase + it * 32 + wl;
    if (n < NWORDS) {
      float* pr = g_pooled + n * H3;
      pr[h]             = fmaxf(m1a + bb1a, 0.f);
      pr[h + 1]         = fmaxf(m1b + bb1b, 0.f);
      pr[H + h]         = fmaxf(m3a + bb3a, 0.f);
      pr[H + h + 1]     = fmaxf(m3b + bb3b, 0.f);
      pr[2 * H + h]     = fmaxf(m5a + bb5a, 0.f);
      pr[2 * H + h + 1] = fmaxf(m5b + bb5b, 0.f);
    }
  }
}

// ================= K2: out = pooled @ lw^T + lb =================
// grid = 148 CTAs (1/SM), each 56 words x 256 h. thread = 7 words x 8 h.
#define KT     64
#define HPAD   257
#define PROW   66          // 64 word slots (8 per wx, 7 used) + 2 pad
#define WPB    56          // words per CTA
#define B_SMEM ((KT * HPAD + KT * PROW) * 4)

__global__ void __launch_bounds__(256, 1) phase_b_kernel(
    const float* __restrict__ lw, const float* __restrict__ lb,
    float* __restrict__ out) {
  extern __shared__ float sm[];
  float* lws = sm;               // [kk][HPAD]
  float* pT  = sm + KT * HPAD;   // [kk][PROW], slot = wx*8 + j (j<7)
  const int tid = threadIdx.x;
  const int hx  = tid & 31;      // warp lanes = consecutive h
  const int wx  = tid >> 5;      // warp id = word group
  const int n0  = blockIdx.x * WPB;

  ull acc[7][4];
#pragma unroll
  for (int j = 0; j < 7; ++j)
#pragma unroll
    for (int u = 0; u < 4; ++u) acc[j][u] = 0ull;

  for (int kt = 0; kt < H3; kt += KT) {
    // stage lw chunk: lws[kk][h] = lw[h*H3 + kt + kk]
#pragma unroll
    for (int i = 0; i < (KT * H) / 256; ++i) {
      int idx = i * 256 + tid;
      int hh = idx >> 6, kk = idx & 63;
      lws[kk * HPAD + hh] = lw[hh * H3 + kt + kk];
    }
    // stage pooled chunk (transposed into slots, OOB -> 0)
#pragma unroll
    for (int i = 0; i < (KT * 64) / 256; ++i) {
      int idx = i * 256 + tid;
      int slot = idx >> 6, kk = idx & 63;
      int jj = slot & 7;
      int wd = n0 + (slot >> 3) * 7 + jj;
      float v = 0.f;
      if (jj < 7 && wd < NWORDS) v = g_pooled[wd * H3 + kt + kk];
      pT[kk * PROW + slot] = v;
    }
    __syncthreads();

#pragma unroll 4
    for (int kk = 0; kk < KT; ++kk) {
      const float* wr = lws + kk * HPAD + hx;
      ull wp0 = pack2(wr[0],   wr[32]);
      ull wp1 = pack2(wr[64],  wr[96]);
      ull wp2 = pack2(wr[128], wr[160]);
      ull wp3 = pack2(wr[192], wr[224]);

      const float* prow = pT + kk * PROW + wx * 8;
      float2 a01 = u2(lds64(prow));
      float2 a23 = u2(lds64(prow + 2));
      float2 a45 = u2(lds64(prow + 4));
      float  p6  = prow[6];
      ull q[7];
      q[0] = pack2(a01.x, a01.x); q[1] = pack2(a01.y, a01.y);
      q[2] = pack2(a23.x, a23.x); q[3] = pack2(a23.y, a23.y);
      q[4] = pack2(a45.x, a45.x); q[5] = pack2(a45.y, a45.y);
      q[6] = pack2(p6, p6);
#pragma unroll
      for (int j = 0; j < 7; ++j) {
        fma2(acc[j][0], q[j], wp0);
        fma2(acc[j][1], q[j], wp1);
        fma2(acc[j][2], q[j], wp2);
        fma2(acc[j][3], q[j], wp3);
      }
    }
    __syncthreads();
  }

  float lbv[8];
#pragma unroll
  for (int u = 0; u < 8; ++u) lbv[u] = lb[hx + 32 * u];
#pragma unroll
  for (int j = 0; j < 7; ++j) {
    int n = n0 + wx * 7 + j;
    if (n < NWORDS) {
      float* o = out + n * H + hx;
#pragma unroll
      for (int u = 0; u < 4; ++u) {
        float2 v = u2(acc[j][u]);
        o[64 * u]      = v.x + lbv[2 * u];
        o[64 * u + 32] = v.y + lbv[2 * u + 1];
      }
    }
  }
}

// ================= launch =================
extern "C" void kernel_launch(void* const* d_in, const int* in_sizes, int n_in,
                              void* d_out, int out_size) {
  const int*   chars = (const int*)d_in[0];
  const float* emb   = (const float*)d_in[1];
  const float* w1    = (const float*)d_in[2];
  const float* b1    = (const float*)d_in[3];
  const float* w3    = (const float*)d_in[4];
  const float* b3    = (const float*)d_in[5];
  const float* w5    = (const float*)d_in[6];
  const float* b5    = (const float*)d_in[7];
  const float* lw    = (const float*)d_in[8];
  const float* lb    = (const float*)d_in[9];
  float* out = (float*)d_out;

  cudaFuncSetAttribute(build_tables_kernel,
                       cudaFuncAttributeMaxDynamicSharedMemorySize, K0_SMEM);
  cudaFuncSetAttribute(phase_a_kernel,
                       cudaFuncAttributeMaxDynamicSharedMemorySize, A_SMEM);
  cudaFuncSetAttribute(phase_b_kernel,
                       cudaFuncAttributeMaxDynamicSharedMemorySize, B_SMEM);

  build_tables_kernel<<<dim3(TAPS, H / 16), 256, K0_SMEM>>>(emb, w1, w3, w5);
  phase_a_kernel<<<dim3(16, 37), 256, A_SMEM>>>(chars, b1, b3, b5);
  phase_b_kernel<<<(NWORDS + WPB - 1) / WPB, 256, B_SMEM>>>(lw, lb, out);
}

// round 3
// speedup vs baseline: 1.7991x; 1.3462x over previous
#include <cuda_runtime.h>

#define NWORDS 8192
#define WLEN   20
#define VOCAB  256
#define E      64
#define H      256
#define TAPS   9
#define H3     768

typedef unsigned long long ull;

__device__ float g_T[TAPS * VOCAB * H];   // [tap][char][h]
__device__ float g_pooled[NWORDS * H3];   // [word][3H]

// ---------------- packed f32x2 helpers ----------------
__device__ __forceinline__ void fma2(ull& d, ull a, ull b) {
  asm("fma.rn.f32x2 %0, %1, %2, %0;" : "+l"(d) : "l"(a), "l"(b));
}
__device__ __forceinline__ ull pack2(float x, float y) {
  ull r; asm("mov.b64 %0, {%1, %2};" : "=l"(r) : "f"(x), "f"(y)); return r;
}
__device__ __forceinline__ float2 u2(ull a) {
  float2 v; asm("mov.b64 {%0, %1}, %2;" : "=f"(v.x), "=f"(v.y) : "l"(a)); return v;
}
__device__ __forceinline__ ull lds64(const float* p) {
  return *reinterpret_cast<const ull*>(p);
}

// ================= K0: build lookup tables =================
#define EPAD 68
#define WPD  66
#define K0_SMEM ((VOCAB * EPAD + 16 * WPD) * 4)

__global__ void __launch_bounds__(256) build_tables_kernel(
    const float* __restrict__ emb, const float* __restrict__ w1,
    const float* __restrict__ w3, const float* __restrict__ w5) {
  extern __shared__ float sm[];
  float* embs = sm;                    // [c][EPAD]
  float* wts  = sm + VOCAB * EPAD;     // [hl][WPD]
  const int t   = blockIdx.x;
  const int h0  = blockIdx.y * 16;
  const int tid = threadIdx.x;
  const int cl  = tid >> 4;
  const int hl  = tid & 15;

  const float4* emb4 = reinterpret_cast<const float4*>(emb);
#pragma unroll
  for (int i = 0; i < 16; ++i) {
    int idx = i * 256 + tid;
    int c = idx >> 4, e4 = idx & 15;
    float4 v = emb4[c * 16 + e4];
    float* d = embs + c * EPAD + e4 * 4;
    d[0] = v.x; d[1] = v.y; d[2] = v.z; d[3] = v.w;
  }
#pragma unroll
  for (int i = 0; i < 4; ++i) {
    int idx = i * 256 + tid;
    int hh = idx >> 6, e = idx & 63;
    int h = h0 + hh;
    float v;
    if (t == 0)      v = w1[h * E + e];
    else if (t <= 3) v = w3[(h * E + e) * 3 + (t - 1)];
    else             v = w5[(h * E + e) * 5 + (t - 4)];
    wts[hh * WPD + e] = v;
  }
  __syncthreads();

  ull acc2[16];
#pragma unroll
  for (int j = 0; j < 16; ++j) acc2[j] = 0ull;

  const ull* wrow = reinterpret_cast<const ull*>(wts + hl * WPD);
  const ull* eb   = reinterpret_cast<const ull*>(embs);
#pragma unroll 4
  for (int e2 = 0; e2 < E / 2; ++e2) {
    ull w2 = wrow[e2];
#pragma unroll
    for (int j = 0; j < 16; ++j)
      fma2(acc2[j], eb[(cl + 16 * j) * (EPAD / 2) + e2], w2);
  }
#pragma unroll
  for (int j = 0; j < 16; ++j) {
    float2 v = u2(acc2[j]);
    g_T[(t * VOCAB + cl + 16 * j) * H + h0 + hl] = v.x + v.y;
  }
}

// ================= K1: conv-as-lookup, conflict-free rows =================
// Branch-split CTAs. Table slice rows = 32 floats (128B, bank-aligned).
// Warp = 1 word x 32 h-lanes; every lookup = one conflict-free 128B wavefront.
#define HC 32
#define TILE_W 64
// branch geometry (592 blocks = exactly 4 waves of 148)
#define NB1_WC 10
#define W1     820
#define NB3_WC 24
#define W3     342
#define NB5_WC 40
#define W5     205
#define NB1 (8 * NB1_WC)   // 80
#define NB3 (8 * NB3_WC)   // 192
#define NB5 (8 * NB5_WC)   // 320
#define NBTOT (NB1 + NB3 + NB5)  // 592
#define A_SMEM ((5 * 256 * HC + TILE_W * WLEN) * 4)   // 168,960 B

__global__ void __launch_bounds__(256, 1) phase_a_kernel(
    const int* __restrict__ chars, const float* __restrict__ b1,
    const float* __restrict__ b3, const float* __restrict__ b5) {
  extern __shared__ float sm[];
  float* Ts = sm;                          // [tl*256 + c][32]
  int*   cs = (int*)(sm + 5 * 256 * HC);   // [64][20]

  const int b   = blockIdx.x;
  const int tid = threadIdx.x;
  const int lane = tid & 31;
  const int warp = tid >> 5;

  int branch, hcb, wstart, wend, ntaps, tapg0;
  if (b < NB1) {
    branch = 0; hcb = b & 7; int wcb = b >> 3;
    wstart = wcb * W1; wend = min(wstart + W1, NWORDS);
    ntaps = 1; tapg0 = 0;
  } else if (b < NB1 + NB3) {
    int r = b - NB1;
    branch = 1; hcb = r & 7; int wcb = r >> 3;
    wstart = wcb * W3; wend = min(wstart + W3, NWORDS);
    ntaps = 3; tapg0 = 1;
  } else {
    int r = b - NB1 - NB3;
    branch = 2; hcb = r & 7; int wcb = r >> 3;
    wstart = wcb * W5; wend = min(wstart + W5, NWORDS);
    ntaps = 5; tapg0 = 4;
  }
  const int h0 = hcb * HC;

  // stage table slice: ntaps*256 rows of 32 floats (float4)
  const int nf4 = ntaps * 256 * 8;
  for (int i = tid; i < nf4; i += 256) {
    int row = i >> 3, q = i & 7;     // row = tl*256 + c
    const float4 v = *reinterpret_cast<const float4*>(
        g_T + (tapg0 * 256 + row) * H + h0 + q * 4);
    *reinterpret_cast<float4*>(Ts + row * HC + q * 4) = v;
  }

  const float* bsel = (branch == 0) ? b1 : ((branch == 1) ? b3 : b5);
  const float bias = bsel[h0 + lane];
  float* outp = g_pooled + branch * H + h0 + lane;

  for (int t0 = wstart; t0 < wend; t0 += TILE_W) {
    const int tn = min(TILE_W, wend - t0);
    __syncthreads();   // table staged (first iter) / prior readers done
    {
      const int4* src = reinterpret_cast<const int4*>(chars + t0 * WLEN);
      int4* dst = reinterpret_cast<int4*>(cs);
      for (int i = tid; i < tn * 5; i += 256) dst[i] = src[i];
    }
    __syncthreads();

    for (int i = warp; i < tn; i += 8) {
      const int4* cw = reinterpret_cast<const int4*>(cs + i * WLEN);
      int4 q0 = cw[0], q1 = cw[1], q2 = cw[2], q3 = cw[3], q4 = cw[4];
      int cc[WLEN];
      cc[0]=q0.x; cc[1]=q0.y; cc[2]=q0.z; cc[3]=q0.w;
      cc[4]=q1.x; cc[5]=q1.y; cc[6]=q1.z; cc[7]=q1.w;
      cc[8]=q2.x; cc[9]=q2.y; cc[10]=q2.z; cc[11]=q2.w;
      cc[12]=q3.x; cc[13]=q3.y; cc[14]=q3.z; cc[15]=q3.w;
      cc[16]=q4.x; cc[17]=q4.y; cc[18]=q4.z; cc[19]=q4.w;
#pragma unroll
      for (int p = 0; p < WLEN; ++p) cc[p] = cc[p] * HC + lane;

      float m = -3e38f;
      if (branch == 0) {
#pragma unroll
        for (int p = 0; p < WLEN; ++p) m = fmaxf(m, Ts[cc[p]]);
      } else if (branch == 1) {
        // taps local 0,1,2 == global 1,2,3 (j=0,1,2)
#pragma unroll
        for (int p = 0; p < WLEN; ++p) {
          float s = Ts[8192 + cc[p]];                 // j=1 (center)
          if (p >= 1)       s += Ts[cc[p - 1]];       // j=0
          if (p < WLEN - 1) s += Ts[16384 + cc[p + 1]]; // j=2
          m = fmaxf(m, s);
        }
      } else {
        // taps local 0..4 == global 4..8 (j=0..4)
#pragma unroll
        for (int p = 0; p < WLEN; ++p) {
          float s = Ts[16384 + cc[p]];                  // j=2 (center)
          if (p >= 2)       s += Ts[cc[p - 2]];         // j=0
          if (p >= 1)       s += Ts[8192 + cc[p - 1]];  // j=1
          if (p < WLEN - 1) s += Ts[24576 + cc[p + 1]]; // j=3
          if (p < WLEN - 2) s += Ts[32768 + cc[p + 2]]; // j=4
          m = fmaxf(m, s);
        }
      }
      outp[(t0 + i) * H3] = fmaxf(m + bias, 0.f);
    }
  }
}

// ================= K2: out = pooled @ lw^T + lb =================
#define KT     64
#define HPAD   257
#define PROW   66
#define WPB    56
#define B_SMEM ((KT * HPAD + KT * PROW) * 4)

__global__ void __launch_bounds__(256, 1) phase_b_kernel(
    const float* __restrict__ lw, const float* __restrict__ lb,
    float* __restrict__ out) {
  extern __shared__ float sm[];
  float* lws = sm;
  float* pT  = sm + KT * HPAD;
  const int tid = threadIdx.x;
  const int hx  = tid & 31;
  const int wx  = tid >> 5;
  const int n0  = blockIdx.x * WPB;

  ull acc[7][4];
#pragma unroll
  for (int j = 0; j < 7; ++j)
#pragma unroll
    for (int u = 0; u < 4; ++u) acc[j][u] = 0ull;

  for (int kt = 0; kt < H3; kt += KT) {
#pragma unroll
    for (int i = 0; i < (KT * H) / 256; ++i) {
      int idx = i * 256 + tid;
      int hh = idx >> 6, kk = idx & 63;
      lws[kk * HPAD + hh] = lw[hh * H3 + kt + kk];
    }
#pragma unroll
    for (int i = 0; i < (KT * 64) / 256; ++i) {
      int idx = i * 256 + tid;
      int slot = idx >> 6, kk = idx & 63;
      int jj = slot & 7;
      int wd = n0 + (slot >> 3) * 7 + jj;
      float v = 0.f;
      if (jj < 7 && wd < NWORDS) v = g_pooled[wd * H3 + kt + kk];
      pT[kk * PROW + slot] = v;
    }
    __syncthreads();

#pragma unroll 4
    for (int kk = 0; kk < KT; ++kk) {
      const float* wr = lws + kk * HPAD + hx;
      ull wp0 = pack2(wr[0],   wr[32]);
      ull wp1 = pack2(wr[64],  wr[96]);
      ull wp2 = pack2(wr[128], wr[160]);
      ull wp3 = pack2(wr[192], wr[224]);

      const float* prow = pT + kk * PROW + wx * 8;
      float2 a01 = u2(lds64(prow));
      float2 a23 = u2(lds64(prow + 2));
      float2 a45 = u2(lds64(prow + 4));
      float  p6  = prow[6];
      ull q[7];
      q[0] = pack2(a01.x, a01.x); q[1] = pack2(a01.y, a01.y);
      q[2] = pack2(a23.x, a23.x); q[3] = pack2(a23.y, a23.y);
      q[4] = pack2(a45.x, a45.x); q[5] = pack2(a45.y, a45.y);
      q[6] = pack2(p6, p6);
#pragma unroll
      for (int j = 0; j < 7; ++j) {
        fma2(acc[j][0], q[j], wp0);
        fma2(acc[j][1], q[j], wp1);
        fma2(acc[j][2], q[j], wp2);
        fma2(acc[j][3], q[j], wp3);
      }
    }
    __syncthreads();
  }

  float lbv[8];
#pragma unroll
  for (int u = 0; u < 8; ++u) lbv[u] = lb[hx + 32 * u];
#pragma unroll
  for (int j = 0; j < 7; ++j) {
    int n = n0 + wx * 7 + j;
    if (n < NWORDS) {
      float* o = out + n * H + hx;
#pragma unroll
      for (int u = 0; u < 4; ++u) {
        float2 v = u2(acc[j][u]);
        o[64 * u]      = v.x + lbv[2 * u];
        o[64 * u + 32] = v.y + lbv[2 * u + 1];
      }
    }
  }
}

// ================= launch =================
extern "C" void kernel_launch(void* const* d_in, const int* in_sizes, int n_in,
                              void* d_out, int out_size) {
  const int*   chars = (const int*)d_in[0];
  const float* emb   = (const float*)d_in[1];
  const float* w1    = (const float*)d_in[2];
  const float* b1    = (const float*)d_in[3];
  const float* w3    = (const float*)d_in[4];
  const float* b3    = (const float*)d_in[5];
  const float* w5    = (const float*)d_in[6];
  const float* b5    = (const float*)d_in[7];
  const float* lw    = (const float*)d_in[8];
  const float* lb    = (const float*)d_in[9];
  float* out = (float*)d_out;

  cudaFuncSetAttribute(build_tables_kernel,
                       cudaFuncAttributeMaxDynamicSharedMemorySize, K0_SMEM);
  cudaFuncSetAttribute(phase_a_kernel,
                       cudaFuncAttributeMaxDynamicSharedMemorySize, A_SMEM);
  cudaFuncSetAttribute(phase_b_kernel,
                       cudaFuncAttributeMaxDynamicSharedMemorySize, B_SMEM);

  build_tables_kernel<<<dim3(TAPS, H / 16), 256, K0_SMEM>>>(emb, w1, w3, w5);
  phase_a_kernel<<<NBTOT, 256, A_SMEM>>>(chars, b1, b3, b5);
  phase_b_kernel<<<(NWORDS + WPB - 1) / WPB, 256, B_SMEM>>>(lw, lb, out);
}

// round 4
// speedup vs baseline: 2.1849x; 1.2145x over previous
#include <cuda_runtime.h>
#include <cuda_fp16.h>

#define NWORDS 8192
#define WLEN   20
#define VOCAB  256
#define E      64
#define H      256
#define TAPS   9
#define H3     768

typedef unsigned long long ull;

__device__ __half g_Th[TAPS * VOCAB * H];   // [tap][char][h] fp16
__device__ float  g_pooled[NWORDS * H3];    // [word][3H]

// ---------------- packed f32x2 helpers ----------------
__device__ __forceinline__ void fma2(ull& d, ull a, ull b) {
  asm("fma.rn.f32x2 %0, %1, %2, %0;" : "+l"(d) : "l"(a), "l"(b));
}
__device__ __forceinline__ ull pack2(float x, float y) {
  ull r; asm("mov.b64 %0, {%1, %2};" : "=l"(r) : "f"(x), "f"(y)); return r;
}
__device__ __forceinline__ float2 u2(ull a) {
  float2 v; asm("mov.b64 {%0, %1}, %2;" : "=f"(v.x), "=f"(v.y) : "l"(a)); return v;
}
__device__ __forceinline__ ull lds64(const float* p) {
  return *reinterpret_cast<const ull*>(p);
}

// ================= K0: build lookup tables (fp16 output) =================
// grid (TAPS, 16 h-chunks, 2 c-halves), 256 thr = 16 c x 16 h
#define EPAD 68
#define WPD  66
#define K0_SMEM ((128 * EPAD + 16 * WPD) * 4)

__global__ void __launch_bounds__(256) build_tables_kernel(
    const float* __restrict__ emb, const float* __restrict__ w1,
    const float* __restrict__ w3, const float* __restrict__ w5) {
  extern __shared__ float sm[];
  float* embs = sm;                    // [128][EPAD]
  float* wts  = sm + 128 * EPAD;       // [16][WPD]
  const int t   = blockIdx.x;
  const int h0  = blockIdx.y * 16;
  const int c0  = blockIdx.z * 128;
  const int tid = threadIdx.x;
  const int cl  = tid >> 4;
  const int hl  = tid & 15;

  const float4* emb4 = reinterpret_cast<const float4*>(emb);
#pragma unroll
  for (int i = 0; i < 8; ++i) {
    int idx = i * 256 + tid;           // < 2048
    int c = idx >> 4, e4 = idx & 15;
    float4 v = emb4[(c0 + c) * 16 + e4];
    float* d = embs + c * EPAD + e4 * 4;
    d[0] = v.x; d[1] = v.y; d[2] = v.z; d[3] = v.w;
  }
#pragma unroll
  for (int i = 0; i < 4; ++i) {
    int idx = i * 256 + tid;
    int hh = idx >> 6, e = idx & 63;
    int h = h0 + hh;
    float v;
    if (t == 0)      v = w1[h * E + e];
    else if (t <= 3) v = w3[(h * E + e) * 3 + (t - 1)];
    else             v = w5[(h * E + e) * 5 + (t - 4)];
    wts[hh * WPD + e] = v;
  }
  __syncthreads();

  ull acc2[8];
#pragma unroll
  for (int j = 0; j < 8; ++j) acc2[j] = 0ull;

  const ull* wrow = reinterpret_cast<const ull*>(wts + hl * WPD);
  const ull* eb   = reinterpret_cast<const ull*>(embs);
#pragma unroll 4
  for (int e2 = 0; e2 < E / 2; ++e2) {
    ull w2 = wrow[e2];
#pragma unroll
    for (int j = 0; j < 8; ++j)
      fma2(acc2[j], eb[(cl + 16 * j) * (EPAD / 2) + e2], w2);
  }
#pragma unroll
  for (int j = 0; j < 8; ++j) {
    float2 v = u2(acc2[j]);
    g_Th[(t * VOCAB + c0 + cl + 16 * j) * H + h0 + hl] =
        __float2half(v.x + v.y);
  }
}

// ================= K1: conv-as-lookup, fp16 tables, 64h rows =================
// Table slice rows = 64 halfs (128B). Warp = 1 word x 32 half2-lanes (64 h).
#define HC 64
#define TILE_W 64
// branch geometry: 592 blocks = exactly 4 waves; 4 h-slices per branch
#define NB1 64            // 16 word-chunks x 4 slices
#define W1  512
#define NB3 188           // 47 x 4
#define W3  175
#define NB5 340           // 85 x 4
#define W5  97
#define NBTOT (NB1 + NB3 + NB5)   // 592
#define A_TBL_BYTES (5 * 256 * HC * 2)            // 163840
#define A_SMEM (A_TBL_BYTES + TILE_W * WLEN * 4)  // 168960

__global__ void __launch_bounds__(256, 1) phase_a_kernel(
    const int* __restrict__ chars, const float* __restrict__ b1,
    const float* __restrict__ b3, const float* __restrict__ b5) {
  extern __shared__ char smA[];
  __half2* Th = reinterpret_cast<__half2*>(smA);     // [tl*256+c][32]
  int* cs = reinterpret_cast<int*>(smA + A_TBL_BYTES);

  const int b    = blockIdx.x;
  const int tid  = threadIdx.x;
  const int lane = tid & 31;
  const int warp = tid >> 5;

  int branch, slice, wstart, wend, ntaps, tapg0;
  if (b < NB1) {
    branch = 0; slice = b & 3; int wcb = b >> 2;
    wstart = wcb * W1; wend = min(wstart + W1, NWORDS);
    ntaps = 1; tapg0 = 0;
  } else if (b < NB1 + NB3) {
    int r = b - NB1;
    branch = 1; slice = r & 3; int wcb = r >> 2;
    wstart = wcb * W3; wend = min(wstart + W3, NWORDS);
    ntaps = 3; tapg0 = 1;
  } else {
    int r = b - NB1 - NB3;
    branch = 2; slice = r & 3; int wcb = r >> 2;
    wstart = wcb * W5; wend = min(wstart + W5, NWORDS);
    ntaps = 5; tapg0 = 4;
  }
  const int h0 = slice * HC;

  // stage table slice: ntaps*256 rows x 128B, linear dst
  {
    const int nf4 = ntaps * 2048;
    int4* dst = reinterpret_cast<int4*>(smA);
    for (int i = tid; i < nf4; i += 256) {
      int row = i >> 3, q = i & 7;
      dst[i] = *(reinterpret_cast<const int4*>(
          g_Th + (tapg0 * 256 + row) * H + h0) + q);
    }
  }

  const float* bsel = (branch == 0) ? b1 : ((branch == 1) ? b3 : b5);
  const __half2 bias =
      __floats2half2_rn(bsel[h0 + 2 * lane], bsel[h0 + 2 * lane + 1]);
  const __half2 zero = __float2half2_rn(0.f);
  const __half2 ninf = __float2half2_rn(-60000.f);

  for (int t0 = wstart; t0 < wend; t0 += TILE_W) {
    const int tn = min(TILE_W, wend - t0);
    __syncthreads();   // tables staged (first iter) / prior readers done
    {
      const int4* src = reinterpret_cast<const int4*>(chars + t0 * WLEN);
      int4* dst = reinterpret_cast<int4*>(cs);
      for (int i = tid; i < tn * 5; i += 256) dst[i] = src[i];
    }
    __syncthreads();

    for (int i = warp; i < tn; i += 8) {
      const int4* cw = reinterpret_cast<const int4*>(cs + i * WLEN);
      int4 q0 = cw[0], q1 = cw[1], q2 = cw[2], q3 = cw[3], q4 = cw[4];
      int cc[WLEN];
      cc[0]=q0.x; cc[1]=q0.y; cc[2]=q0.z; cc[3]=q0.w;
      cc[4]=q1.x; cc[5]=q1.y; cc[6]=q1.z; cc[7]=q1.w;
      cc[8]=q2.x; cc[9]=q2.y; cc[10]=q2.z; cc[11]=q2.w;
      cc[12]=q3.x; cc[13]=q3.y; cc[14]=q3.z; cc[15]=q3.w;
      cc[16]=q4.x; cc[17]=q4.y; cc[18]=q4.z; cc[19]=q4.w;
#pragma unroll
      for (int p = 0; p < WLEN; ++p) cc[p] = cc[p] * 32 + lane;

      __half2 m = ninf;
      if (branch == 0) {
#pragma unroll
        for (int p = 0; p < WLEN; ++p) m = __hmax2(m, Th[cc[p]]);
      } else if (branch == 1) {
#pragma unroll
        for (int p = 0; p < WLEN; ++p) {
          __half2 s = Th[8192 + cc[p]];                      // j=1 center
          if (p >= 1)       s = __hadd2(s, Th[cc[p - 1]]);   // j=0
          if (p < WLEN - 1) s = __hadd2(s, Th[16384 + cc[p + 1]]); // j=2
          m = __hmax2(m, s);
        }
      } else {
#pragma unroll
        for (int p = 0; p < WLEN; ++p) {
          __half2 s = Th[16384 + cc[p]];                     // j=2 center
          if (p >= 2)       s = __hadd2(s, Th[cc[p - 2]]);
          if (p >= 1)       s = __hadd2(s, Th[8192 + cc[p - 1]]);
          if (p < WLEN - 1) s = __hadd2(s, Th[24576 + cc[p + 1]]);
          if (p < WLEN - 2) s = __hadd2(s, Th[32768 + cc[p + 2]]);
          m = __hmax2(m, s);
        }
      }
      __half2 r = __hmax2(__hadd2(m, bias), zero);
      float2 f = __half22float2(r);
      float2* op = reinterpret_cast<float2*>(
          g_pooled + (t0 + i) * H3 + branch * H + h0);
      op[lane] = f;
    }
  }
}

// ================= K2: out = pooled @ lw^T + lb =================
#define KT     64
#define HPAD   257
#define PROW   66
#define WPB    56
#define B_SMEM ((KT * HPAD + KT * PROW) * 4)

__global__ void __launch_bounds__(256, 1) phase_b_kernel(
    const float* __restrict__ lw, const float* __restrict__ lb,
    float* __restrict__ out) {
  extern __shared__ float sm[];
  float* lws = sm;
  float* pT  = sm + KT * HPAD;
  const int tid = threadIdx.x;
  const int hx  = tid & 31;
  const int wx  = tid >> 5;
  const int n0  = blockIdx.x * WPB;

  ull acc[7][4];
#pragma unroll
  for (int j = 0; j < 7; ++j)
#pragma unroll
    for (int u = 0; u < 4; ++u) acc[j][u] = 0ull;

  for (int kt = 0; kt < H3; kt += KT) {
#pragma unroll
    for (int i = 0; i < (KT * H) / 256; ++i) {
      int idx = i * 256 + tid;
      int hh = idx >> 6, kk = idx & 63;
      lws[kk * HPAD + hh] = lw[hh * H3 + kt + kk];
    }
#pragma unroll
    for (int i = 0; i < (KT * 64) / 256; ++i) {
      int idx = i * 256 + tid;
      int slot = idx >> 6, kk = idx & 63;
      int jj = slot & 7;
      int wd = n0 + (slot >> 3) * 7 + jj;
      float v = 0.f;
      if (jj < 7 && wd < NWORDS) v = g_pooled[wd * H3 + kt + kk];
      pT[kk * PROW + slot] = v;
    }
    __syncthreads();

#pragma unroll 4
    for (int kk = 0; kk < KT; ++kk) {
      const float* wr = lws + kk * HPAD + hx;
      ull wp0 = pack2(wr[0],   wr[32]);
      ull wp1 = pack2(wr[64],  wr[96]);
      ull wp2 = pack2(wr[128], wr[160]);
      ull wp3 = pack2(wr[192], wr[224]);

      const float* prow = pT + kk * PROW + wx * 8;
      float2 a01 = u2(lds64(prow));
      float2 a23 = u2(lds64(prow + 2));
      float2 a45 = u2(lds64(prow + 4));
      float  p6  = prow[6];
      ull q[7];
      q[0] = pack2(a01.x, a01.x); q[1] = pack2(a01.y, a01.y);
      q[2] = pack2(a23.x, a23.x); q[3] = pack2(a23.y, a23.y);
      q[4] = pack2(a45.x, a45.x); q[5] = pack2(a45.y, a45.y);
      q[6] = pack2(p6, p6);
#pragma unroll
      for (int j = 0; j < 7; ++j) {
        fma2(acc[j][0], q[j], wp0);
        fma2(acc[j][1], q[j], wp1);
        fma2(acc[j][2], q[j], wp2);
        fma2(acc[j][3], q[j], wp3);
      }
    }
    __syncthreads();
  }

  float lbv[8];
#pragma unroll
  for (int u = 0; u < 8; ++u) lbv[u] = lb[hx + 32 * u];
#pragma unroll
  for (int j = 0; j < 7; ++j) {
    int n = n0 + wx * 7 + j;
    if (n < NWORDS) {
      float* o = out + n * H + hx;
#pragma unroll
      for (int u = 0; u < 4; ++u) {
        float2 v = u2(acc[j][u]);
        o[64 * u]      = v.x + lbv[2 * u];
        o[64 * u + 32] = v.y + lbv[2 * u + 1];
      }
    }
  }
}

// ================= launch =================
extern "C" void kernel_launch(void* const* d_in, const int* in_sizes, int n_in,
                              void* d_out, int out_size) {
  const int*   chars = (const int*)d_in[0];
  const float* emb   = (const float*)d_in[1];
  const float* w1    = (const float*)d_in[2];
  const float* b1    = (const float*)d_in[3];
  const float* w3    = (const float*)d_in[4];
  const float* b3    = (const float*)d_in[5];
  const float* w5    = (const float*)d_in[6];
  const float* b5    = (const float*)d_in[7];
  const float* lw    = (const float*)d_in[8];
  const float* lb    = (const float*)d_in[9];
  float* out = (float*)d_out;

  cudaFuncSetAttribute(build_tables_kernel,
                       cudaFuncAttributeMaxDynamicSharedMemorySize, K0_SMEM);
  cudaFuncSetAttribute(phase_a_kernel,
                       cudaFuncAttributeMaxDynamicSharedMemorySize, A_SMEM);
  cudaFuncSetAttribute(phase_b_kernel,
                       cudaFuncAttributeMaxDynamicSharedMemorySize, B_SMEM);

  build_tables_kernel<<<dim3(TAPS, H / 16, 2), 256, K0_SMEM>>>(emb, w1, w3, w5);
  phase_a_kernel<<<NBTOT, 256, A_SMEM>>>(chars, b1, b3, b5);
  phase_b_kernel<<<(NWORDS + WPB - 1) / WPB, 256, B_SMEM>>>(lw, lb, out);
}

// round 5
// speedup vs baseline: 4.9149x; 2.2495x over previous
#include <cuda_runtime.h>
#include <cuda_fp16.h>
#include <cstdint>

#define NWORDS 8192
#define WLEN   20
#define VOCAB  256
#define E      64
#define H      256
#define TAPS   9
#define H3     768

typedef unsigned long long ull;

__device__ __half g_Th[TAPS * VOCAB * H];   // [tap][char][h] fp16 tables
__device__ __half g_pooledh[NWORDS * H3];   // [word][3H] fp16
__device__ __half g_lwh[H * H3];            // lw in fp16

// ---------------- helpers ----------------
__device__ __forceinline__ void fma2(ull& d, ull a, ull b) {
  asm("fma.rn.f32x2 %0, %1, %2, %0;" : "+l"(d) : "l"(a), "l"(b));
}
__device__ __forceinline__ float2 u2(ull a) {
  float2 v; asm("mov.b64 {%0, %1}, %2;" : "=f"(v.x), "=f"(v.y) : "l"(a)); return v;
}
__device__ __forceinline__ unsigned smem_u32(const void* p) {
  return (unsigned)__cvta_generic_to_shared(p);
}
__device__ __forceinline__ unsigned swz(unsigned off) {
  return off ^ ((off >> 3) & 0x70);
}
__device__ __forceinline__ void cpasync16(unsigned dst, const void* src) {
  asm volatile("cp.async.cg.shared.global [%0], [%1], 16;" :: "r"(dst), "l"(src));
}
__device__ __forceinline__ void cp_commit() {
  asm volatile("cp.async.commit_group;" ::: "memory");
}
__device__ __forceinline__ void cp_wait0() {
  asm volatile("cp.async.wait_group 0;" ::: "memory");
}
__device__ __forceinline__ void ldsm4(uint32_t* r, unsigned addr) {
  asm volatile("ldmatrix.sync.aligned.m8n8.x4.shared.b16 {%0,%1,%2,%3}, [%4];"
               : "=r"(r[0]), "=r"(r[1]), "=r"(r[2]), "=r"(r[3]) : "r"(addr));
}
__device__ __forceinline__ void mma16816(float* d, const uint32_t* a,
                                         uint32_t b0, uint32_t b1) {
  asm volatile(
      "mma.sync.aligned.m16n8k16.row.col.f32.f16.f16.f32 "
      "{%0,%1,%2,%3}, {%4,%5,%6,%7}, {%8,%9}, {%0,%1,%2,%3};"
      : "+f"(d[0]), "+f"(d[1]), "+f"(d[2]), "+f"(d[3])
      : "r"(a[0]), "r"(a[1]), "r"(a[2]), "r"(a[3]), "r"(b0), "r"(b1));
}

// ================= K0: build fp16 lookup tables =================
#define EPAD 68
#define WPD  66
#define K0_SMEM ((128 * EPAD + 16 * WPD) * 4)

__global__ void __launch_bounds__(256) build_tables_kernel(
    const float* __restrict__ emb, const float* __restrict__ w1,
    const float* __restrict__ w3, const float* __restrict__ w5) {
  extern __shared__ float sm0[];
  float* embs = sm0;
  float* wts  = sm0 + 128 * EPAD;
  const int t   = blockIdx.x;
  const int h0  = blockIdx.y * 16;
  const int c0  = blockIdx.z * 128;
  const int tid = threadIdx.x;
  const int cl  = tid >> 4;
  const int hl  = tid & 15;

  const float4* emb4 = reinterpret_cast<const float4*>(emb);
#pragma unroll
  for (int i = 0; i < 8; ++i) {
    int idx = i * 256 + tid;
    int c = idx >> 4, e4 = idx & 15;
    float4 v = emb4[(c0 + c) * 16 + e4];
    float* d = embs + c * EPAD + e4 * 4;
    d[0] = v.x; d[1] = v.y; d[2] = v.z; d[3] = v.w;
  }
#pragma unroll
  for (int i = 0; i < 4; ++i) {
    int idx = i * 256 + tid;
    int hh = idx >> 6, e = idx & 63;
    int h = h0 + hh;
    float v;
    if (t == 0)      v = w1[h * E + e];
    else if (t <= 3) v = w3[(h * E + e) * 3 + (t - 1)];
    else             v = w5[(h * E + e) * 5 + (t - 4)];
    wts[hh * WPD + e] = v;
  }
  __syncthreads();

  ull acc2[8];
#pragma unroll
  for (int j = 0; j < 8; ++j) acc2[j] = 0ull;
  const ull* wrow = reinterpret_cast<const ull*>(wts + hl * WPD);
  const ull* eb   = reinterpret_cast<const ull*>(embs);
#pragma unroll 4
  for (int e2 = 0; e2 < E / 2; ++e2) {
    ull w2 = wrow[e2];
#pragma unroll
    for (int j = 0; j < 8; ++j)
      fma2(acc2[j], eb[(cl + 16 * j) * (EPAD / 2) + e2], w2);
  }
#pragma unroll
  for (int j = 0; j < 8; ++j) {
    float2 v = u2(acc2[j]);
    g_Th[(t * VOCAB + c0 + cl + 16 * j) * H + h0 + hl] = __float2half(v.x + v.y);
  }
}

// ================= K0b: lw -> fp16 =================
__global__ void __launch_bounds__(256) lwh_kernel(const float* __restrict__ lw) {
  int idx = blockIdx.x * 256 + threadIdx.x;   // over 49152 float4
  float4 v = reinterpret_cast<const float4*>(lw)[idx];
  __half2* dst = reinterpret_cast<__half2*>(g_lwh);
  dst[idx * 2]     = __floats2half2_rn(v.x, v.y);
  dst[idx * 2 + 1] = __floats2half2_rn(v.z, v.w);
}

// ================= K1: conv-as-lookup, fp16, 512 threads =================
#define HC 64
#define TILE_W 128
#define NB1 64
#define W1  512
#define NB3 188
#define W3  175
#define NB5 340
#define W5  97
#define NBTOT (NB1 + NB3 + NB5)   // 592 = 4 waves
#define A_TBL_BYTES (5 * 256 * HC * 2)            // 163840
#define A_SMEM (A_TBL_BYTES + TILE_W * WLEN * 4)  // 174080

__global__ void __launch_bounds__(512, 1) phase_a_kernel(
    const int* __restrict__ chars, const float* __restrict__ b1,
    const float* __restrict__ b3, const float* __restrict__ b5) {
  extern __shared__ char smA[];
  __half2* Th = reinterpret_cast<__half2*>(smA);
  int* cs = reinterpret_cast<int*>(smA + A_TBL_BYTES);

  const int b    = blockIdx.x;
  const int tid  = threadIdx.x;
  const int lane = tid & 31;
  const int warp = tid >> 5;   // 0..15

  int branch, slice, wstart, wend, ntaps, tapg0;
  if (b < NB1) {
    branch = 0; slice = b & 3; int wcb = b >> 2;
    wstart = wcb * W1; wend = min(wstart + W1, NWORDS);
    ntaps = 1; tapg0 = 0;
  } else if (b < NB1 + NB3) {
    int r = b - NB1;
    branch = 1; slice = r & 3; int wcb = r >> 2;
    wstart = wcb * W3; wend = min(wstart + W3, NWORDS);
    ntaps = 3; tapg0 = 1;
  } else {
    int r = b - NB1 - NB3;
    branch = 2; slice = r & 3; int wcb = r >> 2;
    wstart = wcb * W5; wend = min(wstart + W5, NWORDS);
    ntaps = 5; tapg0 = 4;
  }
  const int h0 = slice * HC;

  {
    const int nf4 = ntaps * 2048;
    int4* dst = reinterpret_cast<int4*>(smA);
    for (int i = tid; i < nf4; i += 512) {
      int row = i >> 3, q = i & 7;
      dst[i] = *(reinterpret_cast<const int4*>(
          g_Th + (tapg0 * 256 + row) * H + h0) + q);
    }
  }

  const float* bsel = (branch == 0) ? b1 : ((branch == 1) ? b3 : b5);
  const __half2 bias =
      __floats2half2_rn(bsel[h0 + 2 * lane], bsel[h0 + 2 * lane + 1]);
  const __half2 zero = __float2half2_rn(0.f);
  const __half2 ninf = __float2half2_rn(-60000.f);

  for (int t0 = wstart; t0 < wend; t0 += TILE_W) {
    const int tn = min(TILE_W, wend - t0);
    __syncthreads();
    {
      const int4* src = reinterpret_cast<const int4*>(chars + t0 * WLEN);
      int4* dst = reinterpret_cast<int4*>(cs);
      for (int i = tid; i < tn * 5; i += 512) dst[i] = src[i];
    }
    __syncthreads();

    for (int i = warp; i < tn; i += 16) {
      const int4* cw = reinterpret_cast<const int4*>(cs + i * WLEN);
      int4 q0 = cw[0], q1 = cw[1], q2 = cw[2], q3 = cw[3], q4 = cw[4];
      int cc[WLEN];
      cc[0]=q0.x; cc[1]=q0.y; cc[2]=q0.z; cc[3]=q0.w;
      cc[4]=q1.x; cc[5]=q1.y; cc[6]=q1.z; cc[7]=q1.w;
      cc[8]=q2.x; cc[9]=q2.y; cc[10]=q2.z; cc[11]=q2.w;
      cc[12]=q3.x; cc[13]=q3.y; cc[14]=q3.z; cc[15]=q3.w;
      cc[16]=q4.x; cc[17]=q4.y; cc[18]=q4.z; cc[19]=q4.w;
#pragma unroll
      for (int p = 0; p < WLEN; ++p) cc[p] = cc[p] * 32 + lane;

      __half2 m = ninf;
      if (branch == 0) {
#pragma unroll
        for (int p = 0; p < WLEN; ++p) m = __hmax2(m, Th[cc[p]]);
      } else if (branch == 1) {
#pragma unroll
        for (int p = 0; p < WLEN; ++p) {
          __half2 s = Th[8192 + cc[p]];
          if (p >= 1)       s = __hadd2(s, Th[cc[p - 1]]);
          if (p < WLEN - 1) s = __hadd2(s, Th[16384 + cc[p + 1]]);
          m = __hmax2(m, s);
        }
      } else {
#pragma unroll
        for (int p = 0; p < WLEN; ++p) {
          __half2 s = Th[16384 + cc[p]];
          if (p >= 2)       s = __hadd2(s, Th[cc[p - 2]]);
          if (p >= 1)       s = __hadd2(s, Th[8192 + cc[p - 1]]);
          if (p < WLEN - 1) s = __hadd2(s, Th[24576 + cc[p + 1]]);
          if (p < WLEN - 2) s = __hadd2(s, Th[32768 + cc[p + 2]]);
          m = __hmax2(m, s);
        }
      }
      __half2 r = __hmax2(__hadd2(m, bias), zero);
      __half2* op = reinterpret_cast<__half2*>(
          g_pooledh + (size_t)(t0 + i) * H3 + branch * H + h0);
      op[lane] = r;
    }
  }
}

// ================= K2: tensor-core GEMM out = pooled @ lw^T + lb =================
// 128 CTAs, 256 thr (8 warps). CTA tile: M=64 words x N=256 h, K=768 in 12
// chunks of 64, cp.async double-buffered. Warp: M=64 x N=32.
#define BM 64
#define KC 64
#define PB_BUF  40960                      // A (8KB) + B (32KB) per stage
#define PB_SMEM (2 * PB_BUF)

__device__ __forceinline__ void pb_prefetch(unsigned sbase, int tid, int m0,
                                            int kc) {
  const int kt = kc * KC;
  unsigned abuf = sbase + (kc & 1) * PB_BUF;
  unsigned bbuf = abuf + 8192;
#pragma unroll
  for (int i = 0; i < 2; ++i) {            // A: 64x64 fp16 = 512 x 16B
    int idx = i * 256 + tid;
    int m = idx >> 3, kq = idx & 7;
    cpasync16(abuf + swz(m * 128 + kq * 16),
              g_pooledh + (size_t)(m0 + m) * H3 + kt + kq * 8);
  }
#pragma unroll
  for (int i = 0; i < 8; ++i) {            // B: 256x64 fp16 = 2048 x 16B
    int idx = i * 256 + tid;
    int h = idx >> 3, kq = idx & 7;
    cpasync16(bbuf + swz(h * 128 + kq * 16),
              g_lwh + (size_t)h * H3 + kt + kq * 8);
  }
  cp_commit();
}

__global__ void __launch_bounds__(256, 1) phase_b_kernel(
    const float* __restrict__ lb, float* __restrict__ out) {
  extern __shared__ char smB[];
  const unsigned sbase = smem_u32(smB);
  const int tid  = threadIdx.x;
  const int lane = tid & 31;
  const int warp = tid >> 5;
  const int m0 = blockIdx.x * BM;
  const int n0 = warp * 32;

  float acc[4][4][4];
#pragma unroll
  for (int mt = 0; mt < 4; ++mt)
#pragma unroll
    for (int nt = 0; nt < 4; ++nt)
#pragma unroll
      for (int u = 0; u < 4; ++u) acc[mt][nt][u] = 0.f;

  pb_prefetch(sbase, tid, m0, 0);

  for (int kc = 0; kc < H3 / KC; ++kc) {
    cp_wait0();
    __syncthreads();
    if (kc + 1 < H3 / KC) pb_prefetch(sbase, tid, m0, kc + 1);

    unsigned abuf = sbase + (kc & 1) * PB_BUF;
    unsigned bbuf = abuf + 8192;
#pragma unroll
    for (int k16 = 0; k16 < 4; ++k16) {
      const unsigned kbyte = k16 * 32 + (lane >> 4) * 16;
      uint32_t a[4][4];
#pragma unroll
      for (int mt = 0; mt < 4; ++mt) {
        unsigned row = mt * 16 + (lane & 15);
        ldsm4(a[mt], abuf + swz(row * 128 + kbyte));
      }
      uint32_t bq[2][4];
#pragma unroll
      for (int nt2 = 0; nt2 < 2; ++nt2) {
        unsigned row = n0 + nt2 * 16 + (lane & 15);
        ldsm4(bq[nt2], bbuf + swz(row * 128 + kbyte));
      }
#pragma unroll
      for (int mt = 0; mt < 4; ++mt)
#pragma unroll
        for (int nt = 0; nt < 4; ++nt)
          mma16816(acc[mt][nt], a[mt],
                   bq[nt >> 1][nt & 1], bq[nt >> 1][2 + (nt & 1)]);
    }
    __syncthreads();
  }

  const int cg = (lane & 3) * 2;
  const int rg = lane >> 2;
#pragma unroll
  for (int nt = 0; nt < 4; ++nt) {
    const int c = n0 + nt * 8 + cg;
    float2 lbv = *reinterpret_cast<const float2*>(lb + c);
#pragma unroll
    for (int mt = 0; mt < 4; ++mt) {
      int r = m0 + mt * 16 + rg;
      float2 v0 = make_float2(acc[mt][nt][0] + lbv.x, acc[mt][nt][1] + lbv.y);
      float2 v1 = make_float2(acc[mt][nt][2] + lbv.x, acc[mt][nt][3] + lbv.y);
      *reinterpret_cast<float2*>(out + (size_t)r * H + c) = v0;
      *reinterpret_cast<float2*>(out + (size_t)(r + 8) * H + c) = v1;
    }
  }
}

// ================= launch =================
extern "C" void kernel_launch(void* const* d_in, const int* in_sizes, int n_in,
                              void* d_out, int out_size) {
  const int*   chars = (const int*)d_in[0];
  const float* emb   = (const float*)d_in[1];
  const float* w1    = (const float*)d_in[2];
  const float* b1    = (const float*)d_in[3];
  const float* w3    = (const float*)d_in[4];
  const float* b3    = (const float*)d_in[5];
  const float* w5    = (const float*)d_in[6];
  const float* b5    = (const float*)d_in[7];
  const float* lw    = (const float*)d_in[8];
  const float* lb    = (const float*)d_in[9];
  float* out = (float*)d_out;

  cudaFuncSetAttribute(build_tables_kernel,
                       cudaFuncAttributeMaxDynamicSharedMemorySize, K0_SMEM);
  cudaFuncSetAttribute(phase_a_kernel,
                       cudaFuncAttributeMaxDynamicSharedMemorySize, A_SMEM);
  cudaFuncSetAttribute(phase_b_kernel,
                       cudaFuncAttributeMaxDynamicSharedMemorySize, PB_SMEM);

  build_tables_kernel<<<dim3(TAPS, H / 16, 2), 256, K0_SMEM>>>(emb, w1, w3, w5);
  lwh_kernel<<<(H * H3 / 4) / 256, 256>>>(lw);
  phase_a_kernel<<<NBTOT, 512, A_SMEM>>>(chars, b1, b3, b5);
  phase_b_kernel<<<NWORDS / BM, 256, PB_SMEM>>>(lb, out);
}